// round 17
// baseline (speedup 1.0000x reference)
#include <cuda_runtime.h>
#include <cuda_fp16.h>
#include <cstdint>

#define BB 2
#define SS 2048
#define EE 1024
#define HH 16
#define DD 64
#define MM (BB*SS)
#define SCALE 0.125f
#define LOG2E 1.44269504f
#define GK 1024
#define GN 1024

// ---------------- scratch ----------------
__device__ __half g_Xh[MM*EE];
__device__ __half g_WT[5][EE*EE];   // 0=q 1=k 2=v 3=g 4=o, [n][k]
__device__ __half g_Qh[MM*EE];
__device__ __half g_Kh[MM*EE];
__device__ __half g_Vt[MM*EE];      // [b][h][d][tok]
__device__ __half g_Gh[MM*EE];      // sigmoid(gate), half
__device__ __half g_O0h[MM*EE];
__device__ __half g_O1h[MM*EE];

// ---------------- helpers ----------------
__device__ __forceinline__ uint32_t smem_u32(const void* p) {
    return (uint32_t)__cvta_generic_to_shared(p);
}
#define CP16(d_, s_) asm volatile("cp.async.cg.shared.global [%0],[%1],16;\n" :: "r"(d_), "l"(s_))
#define CPCOMMIT() asm volatile("cp.async.commit_group;\n")
#define CPWAIT1() asm volatile("cp.async.wait_group 1;\n")
#define CPWAIT0() asm volatile("cp.async.wait_group 0;\n")

__device__ __forceinline__ void mma16(float* d, const uint32_t* a, const uint32_t* b) {
    asm volatile(
        "mma.sync.aligned.m16n8k16.row.col.f32.f16.f16.f32 "
        "{%0,%1,%2,%3}, {%4,%5,%6,%7}, {%8,%9}, {%0,%1,%2,%3};"
        : "+f"(d[0]), "+f"(d[1]), "+f"(d[2]), "+f"(d[3])
        : "r"(a[0]), "r"(a[1]), "r"(a[2]), "r"(a[3]), "r"(b[0]), "r"(b[1]));
}
__device__ __forceinline__ void mma16h(uint32_t* d, const uint32_t* a, const uint32_t* b) {
    asm volatile(
        "mma.sync.aligned.m16n8k16.row.col.f16.f16.f16.f16 "
        "{%0,%1}, {%2,%3,%4,%5}, {%6,%7}, {%0,%1};"
        : "+r"(d[0]), "+r"(d[1])
        : "r"(a[0]), "r"(a[1]), "r"(a[2]), "r"(a[3]), "r"(b[0]), "r"(b[1]));
}
__device__ __forceinline__ uint32_t h2ex2(uint32_t x) {
    uint32_t y;
    asm("ex2.approx.f16x2 %0, %1;" : "=r"(y) : "r"(x));
    return y;
}
__device__ __forceinline__ uint32_t h2addu(uint32_t a, uint32_t b) {
    __half2 r = __hadd2(*(__half2*)&a, *(__half2*)&b);
    return *(uint32_t*)&r;
}

// ---------------- prep (fused): z<5 weight transpose, z==5 x convert -------
__global__ void prep_all(const float* x, const float* Wq, const float* Wk,
                         const float* Wv, const float* Wg, const float* Wo) {
    __shared__ float t[32][33];
    int z = blockIdx.z;
    int tx = threadIdx.x, ty = threadIdx.y;
    if (z == 5) {
        int base = (blockIdx.y * 32 + blockIdx.x) * 256 + ty * 32 + tx;
#pragma unroll 4
        for (int i = base; i < MM * EE / 2; i += 32 * 32 * 256) {
            float2 v = ((const float2*)x)[i];
            ((__half2*)g_Xh)[i] = __floats2half2_rn(v.x, v.y);
        }
        return;
    }
    const float* W = z==0?Wq : z==1?Wk : z==2?Wv : z==3?Wg : Wo;
    __half* D = g_WT[z];
    int n0 = blockIdx.x*32, k0 = blockIdx.y*32;
#pragma unroll
    for (int j = 0; j < 4; ++j)
        t[ty + j*8][tx] = W[(size_t)(k0 + ty + j*8)*GN + n0 + tx];
    __syncthreads();
#pragma unroll
    for (int j = 0; j < 4; ++j)
        D[(size_t)(n0 + ty + j*8)*GK + k0 + tx] = __float2half_rn(t[tx][ty + j*8]);
}

// ---------------- GEMM core: 3-stage cp.async pipeline, 1 barrier/iter ------
// 256 thr, 8 warps (4x2), warp tile 32x64, 128x128x64 tiles.
// Optional A2: A-tile = A + A2 summed at load time (LDG+hadd2+STS).
#define AST 72
#define TILE_H (128*AST)
#define GEMM_SMEM3 (6*TILE_H*2)       // As[3] + Bs[3]

__device__ __forceinline__ void gemm_core(
    const __half* __restrict__ A, const __half* __restrict__ A2,
    const __half* __restrict__ Bt,
    const float* __restrict__ bias, float* __restrict__ fC,
    __half* __restrict__ hC, int mode)
{
    extern __shared__ char smp[];
    __half* As = (__half*)smp;                  // 3 x TILE_H
    __half* Bs = (__half*)smp + 3*TILE_H;       // 3 x TILE_H

    const int tid = threadIdx.x, lane = tid & 31, wid = tid >> 5;
    const int wm = wid >> 1, wn = wid & 1, g = lane >> 2, c = lane & 3;
    const int row0 = blockIdx.y*128, col0 = blockIdx.x*128;

    float acc[2][8][4];
#pragma unroll
    for (int mi = 0; mi < 2; ++mi)
#pragma unroll
        for (int ni = 0; ni < 8; ++ni) {
            acc[mi][ni][0]=0.f; acc[mi][ni][1]=0.f; acc[mi][ni][2]=0.f; acc[mi][ni][3]=0.f;
        }

    auto load_chunk = [&](int buf, int k0) {
#pragma unroll
        for (int u = 0; u < 4; ++u) {
            int idx = tid + u*256, r = idx >> 3, ko = (idx & 7)*8;
            if (!A2) {
                CP16(smem_u32(&As[buf*TILE_H + r*AST + ko]), &A[(size_t)(row0+r)*GK + k0 + ko]);
            } else {
                uint4 va = *(const uint4*)&A[(size_t)(row0+r)*GK + k0 + ko];
                uint4 vb = *(const uint4*)&A2[(size_t)(row0+r)*GK + k0 + ko];
                uint4 vc;
                vc.x = h2addu(va.x, vb.x); vc.y = h2addu(va.y, vb.y);
                vc.z = h2addu(va.z, vb.z); vc.w = h2addu(va.w, vb.w);
                *(uint4*)&As[buf*TILE_H + r*AST + ko] = vc;
            }
            CP16(smem_u32(&Bs[buf*TILE_H + r*AST + ko]), &Bt[(size_t)(col0+r)*GK + k0 + ko]);
        }
        CPCOMMIT();
    };

    load_chunk(0, 0);
    load_chunk(1, 64);

#pragma unroll 1
    for (int it = 0; it < 16; ++it) {
        if (it < 15) { CPWAIT1(); } else { CPWAIT0(); }
        __syncthreads();                       // chunk it visible; chunk it-1 readers done
        if (it < 14) load_chunk((it + 2) % 3, (it + 2)*64);

        const __half* Ab = &As[(it % 3)*TILE_H];
        const __half* Bb = &Bs[(it % 3)*TILE_H];
#pragma unroll
        for (int ks = 0; ks < 4; ++ks) {
            int kb = ks*16;
            uint32_t a[2][4];
#pragma unroll
            for (int mi = 0; mi < 2; ++mi) {
                int r = wm*32 + mi*16 + g;
                a[mi][0] = *(const uint32_t*)&Ab[r*AST + kb + 2*c];
                a[mi][1] = *(const uint32_t*)&Ab[(r+8)*AST + kb + 2*c];
                a[mi][2] = *(const uint32_t*)&Ab[r*AST + kb + 8 + 2*c];
                a[mi][3] = *(const uint32_t*)&Ab[(r+8)*AST + kb + 8 + 2*c];
            }
#pragma unroll
            for (int ni = 0; ni < 8; ++ni) {
                int n = wn*64 + ni*8 + g;
                uint32_t b[2];
                b[0] = *(const uint32_t*)&Bb[n*AST + kb + 2*c];
                b[1] = *(const uint32_t*)&Bb[n*AST + kb + 8 + 2*c];
                mma16(acc[0][ni], a[0], b);
                mma16(acc[1][ni], a[1], b);
            }
        }
    }

#pragma unroll
    for (int mi = 0; mi < 2; ++mi) {
#pragma unroll
        for (int ni = 0; ni < 8; ++ni) {
            int r = row0 + wm*32 + mi*16 + g;
            int col = col0 + wn*64 + ni*8 + 2*c;
            float b0 = 0.f, b1 = 0.f;
            if (bias) { b0 = bias[col]; b1 = bias[col+1]; }
            float v0 = acc[mi][ni][0]+b0, v1 = acc[mi][ni][1]+b1;
            float v2 = acc[mi][ni][2]+b0, v3 = acc[mi][ni][3]+b1;
            if (mode == 0) {
                const float f = SCALE * LOG2E;
                v0*=f; v1*=f; v2*=f; v3*=f;
            }
            if (mode == 4) {
                *(float2*)&fC[(size_t)r*GN + col] = make_float2(v0, v1);
                *(float2*)&fC[(size_t)(r+8)*GN + col] = make_float2(v2, v3);
            } else if (mode == 3) {
                float s0 = 1.f/(1.f+__expf(-v0)), s1 = 1.f/(1.f+__expf(-v1));
                float s2 = 1.f/(1.f+__expf(-v2)), s3 = 1.f/(1.f+__expf(-v3));
                *(__half2*)&hC[(size_t)r*GN + col] = __floats2half2_rn(s0, s1);
                *(__half2*)&hC[(size_t)(r+8)*GN + col] = __floats2half2_rn(s2, s3);
            } else if (mode == 2) {
                int bi = r >> 11, tok = r & 2047, hh = col >> 6, d = col & 63;
                __half* Vb = &g_Vt[(size_t)((bi*HH + hh)*DD) * SS];
                Vb[(size_t)d*SS + tok]       = __float2half_rn(v0);
                Vb[(size_t)(d+1)*SS + tok]   = __float2half_rn(v1);
                Vb[(size_t)d*SS + tok+8]     = __float2half_rn(v2);
                Vb[(size_t)(d+1)*SS + tok+8] = __float2half_rn(v3);
            } else {
                *(__half2*)&hC[(size_t)r*GN + col] = __floats2half2_rn(v0, v1);
                *(__half2*)&hC[(size_t)(r+8)*GN + col] = __floats2half2_rn(v2, v3);
            }
        }
    }
}

__global__ __launch_bounds__(256, 2) void gemm_qkvg(
    const float* bq, const float* bk, const float* bv)
{
    int z = blockIdx.z;
    const float* bias = z==0?bq : z==1?bk : z==2?bv : nullptr;
    __half* hC = z==0?g_Qh : z==1?g_Kh : z==2?nullptr : g_Gh;
    gemm_core(g_Xh, nullptr, g_WT[z], bias, nullptr, hC, z);
}
__global__ __launch_bounds__(256, 2) void gemm_out(const float* bo, float* out)
{
    gemm_core(g_O0h, g_O1h, g_WT[4], bo, out, nullptr, 4);
}

// ---------------- Attention (R13, unchanged): f16-score flash ----------------
#define KST 72
#define Q_OFF 0
#define K_OFF (128*KST)
#define V_OFF (K_OFF + 2*64*KST)
#define MSK_OFF_B ((V_OFF + 2*64*KST)*2)
#define ATT_SMEM (MSK_OFF_B + 128)
#define HINF 0xFC00u
#define HONE2 0x3C003C00u

__global__ __launch_bounds__(128) void attn_h(const unsigned char* __restrict__ mask)
{
    extern __shared__ char smc[];
    __half* Qs = (__half*)smc + Q_OFF;
    __half* Ks = (__half*)smc + K_OFF;
    __half* Vs = (__half*)smc + V_OFF;
    unsigned char* mskb = (unsigned char*)smc + MSK_OFF_B;

    const int tid = threadIdx.x, lane = tid & 31, wid = tid >> 5;
    const int g = lane >> 2, c = lane & 3;
    const int h = blockIdx.y, z = blockIdx.z;
    const int b = z >> 1, p = z & 1;
    const int q0 = blockIdx.x*128, hoff = h*DD;
    const int kbase = p*1024;
    const float pw = p ? 1.0f : 0.5f;
    const int wrow = wid*32;
    const __half* Kg = &g_Kh[(size_t)b*SS*EE + hoff];
    const __half* Vg = &g_Vt[(size_t)(b*HH + h)*DD*SS];

    auto issue = [&](int t) {
        int buf = t & 1, k0g = kbase + t*64;
#pragma unroll
        for (int u = 0; u < 4; ++u) {
            int idx = tid + u*128, r = idx >> 3, ko = (idx & 7)*8;
            CP16(smem_u32(&Ks[buf*64*KST + r*KST + ko]), &Kg[(size_t)(k0g + r)*EE + ko]);
            CP16(smem_u32(&Vs[buf*64*KST + r*KST + ko]), &Vg[(size_t)r*SS + k0g + ko]);
        }
        if (tid < 4)
            CP16(smem_u32(&mskb[(t & 1)*64 + tid*16]), &mask[(size_t)b*SS + k0g + tid*16]);
        CPCOMMIT();
    };

#pragma unroll
    for (int u = 0; u < 8; ++u) {
        int idx = tid + u*128, r = idx >> 3, ko = (idx & 7)*8;
        CP16(smem_u32(&Qs[r*KST + ko]), &g_Qh[(size_t)(b*SS + q0 + r)*EE + hoff + ko]);
    }
    issue(0);

    float o[2][8][4];
    float lac[2][4];
#pragma unroll
    for (int mi = 0; mi < 2; ++mi) {
        lac[mi][0]=0.f; lac[mi][1]=0.f; lac[mi][2]=0.f; lac[mi][3]=0.f;
#pragma unroll
        for (int ni = 0; ni < 8; ++ni) {
            o[mi][ni][0]=0.f; o[mi][ni][1]=0.f; o[mi][ni][2]=0.f; o[mi][ni][3]=0.f;
        }
    }
    const uint32_t ones2[2] = {HONE2, HONE2};

#pragma unroll 1
    for (int t = 0; t < 16; ++t) {
        if (t < 15) { issue(t + 1); CPWAIT1(); } else { CPWAIT0(); }
        __syncthreads();
        const __half* Kb = &Ks[(t & 1)*64*KST];
        const __half* Vb = &Vs[(t & 1)*64*KST];
        const unsigned char* mb = &mskb[(t & 1)*64];

        uint32_t s[2][8][2];
#pragma unroll
        for (int mi = 0; mi < 2; ++mi)
#pragma unroll
            for (int ni = 0; ni < 8; ++ni) { s[mi][ni][0]=0u; s[mi][ni][1]=0u; }
#pragma unroll
        for (int ks = 0; ks < 4; ++ks) {
            int kb = ks*16;
            uint32_t a[2][4];
#pragma unroll
            for (int mi = 0; mi < 2; ++mi) {
                int r = wrow + mi*16 + g;
                a[mi][0] = *(const uint32_t*)&Qs[r*KST + kb + 2*c];
                a[mi][1] = *(const uint32_t*)&Qs[(r+8)*KST + kb + 2*c];
                a[mi][2] = *(const uint32_t*)&Qs[r*KST + kb + 8 + 2*c];
                a[mi][3] = *(const uint32_t*)&Qs[(r+8)*KST + kb + 8 + 2*c];
            }
#pragma unroll
            for (int ni = 0; ni < 8; ++ni) {
                int n = ni*8 + g;
                uint32_t bf[2];
                bf[0] = *(const uint32_t*)&Kb[n*KST + kb + 2*c];
                bf[1] = *(const uint32_t*)&Kb[n*KST + kb + 8 + 2*c];
                mma16h(s[0][ni], a[0], bf);
                mma16h(s[1][ni], a[1], bf);
            }
        }

        uint32_t mh[8];
#pragma unroll
        for (int ni = 0; ni < 8; ++ni)
            mh[ni] = (mb[ni*8 + 2*c] ? HINF : 0u) | (mb[ni*8 + 2*c + 1] ? (HINF << 16) : 0u);
#pragma unroll
        for (int mi = 0; mi < 2; ++mi)
#pragma unroll
            for (int ni = 0; ni < 8; ++ni) {
                s[mi][ni][0] = h2ex2(h2addu(s[mi][ni][0], mh[ni]));
                s[mi][ni][1] = h2ex2(h2addu(s[mi][ni][1], mh[ni]));
            }

#pragma unroll
        for (int kc = 0; kc < 4; ++kc) {
            uint32_t ap[2][4];
#pragma unroll
            for (int mi = 0; mi < 2; ++mi) {
                ap[mi][0] = s[mi][2*kc][0];
                ap[mi][1] = s[mi][2*kc][1];
                ap[mi][2] = s[mi][2*kc+1][0];
                ap[mi][3] = s[mi][2*kc+1][1];
            }
#pragma unroll
            for (int ni = 0; ni < 8; ++ni) {
                int n = ni*8 + g;
                uint32_t bf[2];
                bf[0] = *(const uint32_t*)&Vb[n*KST + kc*16 + 2*c];
                bf[1] = *(const uint32_t*)&Vb[n*KST + kc*16 + 8 + 2*c];
                mma16(o[0][ni], ap[0], bf);
                mma16(o[1][ni], ap[1], bf);
            }
            mma16(lac[0], ap[0], ones2);
            mma16(lac[1], ap[1], ones2);
        }
        __syncthreads();
    }

    __half* Op = p ? g_O1h : g_O0h;
#pragma unroll
    for (int mi = 0; mi < 2; ++mi) {
        const int r0 = q0 + wrow + mi*16 + g, r1 = r0 + 8;
        const float inv0 = pw / lac[mi][0], inv1 = pw / lac[mi][2];
#pragma unroll
        for (int ni = 0; ni < 8; ++ni) {
            int col = hoff + ni*8 + 2*c;
            size_t i0 = (size_t)(b*SS + r0)*EE + col;
            size_t i1 = (size_t)(b*SS + r1)*EE + col;
            float v0 = o[mi][ni][0]*inv0, v1 = o[mi][ni][1]*inv0;
            float v2 = o[mi][ni][2]*inv1, v3 = o[mi][ni][3]*inv1;
            if (r0 >= 1) {
                __half2 gh = *(const __half2*)&g_Gh[i0];
                v0 *= __half2float(gh.x);
                v1 *= __half2float(gh.y);
            }
            __half2 gw = *(const __half2*)&g_Gh[i1];
            v2 *= __half2float(gw.x);
            v3 *= __half2float(gw.y);
            *(__half2*)&Op[i0] = __floats2half2_rn(v0, v1);
            *(__half2*)&Op[i1] = __floats2half2_rn(v2, v3);
        }
    }
}

// ---------------- launch ----------------
extern "C" void kernel_launch(void* const* d_in, const int* in_sizes, int n_in,
                              void* d_out, int out_size)
{
    const float* x  = (const float*)d_in[0];
    const float* Wq = (const float*)d_in[1];
    const float* bq = (const float*)d_in[2];
    const float* Wk = (const float*)d_in[3];
    const float* bk = (const float*)d_in[4];
    const float* Wv = (const float*)d_in[5];
    const float* bv = (const float*)d_in[6];
    const float* Wo = (const float*)d_in[7];
    const float* bo = (const float*)d_in[8];
    const float* Wg = (const float*)d_in[9];
    const unsigned char* mask = (const unsigned char*)d_in[10];
    float* out = (float*)d_out;

    static int attr_set = 0;
    if (!attr_set) {
        cudaFuncSetAttribute(gemm_qkvg, cudaFuncAttributeMaxDynamicSharedMemorySize, GEMM_SMEM3);
        cudaFuncSetAttribute(gemm_out,  cudaFuncAttributeMaxDynamicSharedMemorySize, GEMM_SMEM3);
        cudaFuncSetAttribute(attn_h,    cudaFuncAttributeMaxDynamicSharedMemorySize, ATT_SMEM);
        attr_set = 1;
    }

    prep_all<<<dim3(32, 32, 6), dim3(32, 8)>>>(x, Wq, Wk, Wv, Wg, Wo);
    gemm_qkvg<<<dim3(8, 32, 4), 256, GEMM_SMEM3>>>(bq, bk, bv);
    attn_h<<<dim3(SS/128, HH, BB*2), 128, ATT_SMEM>>>(mask);
    gemm_out<<<dim3(8, 32), 256, GEMM_SMEM3>>>(bo, out);
}